// round 1
// baseline (speedup 1.0000x reference)
#include <cuda_runtime.h>
#include <cuda_bf16.h>
#include <math.h>

#define NN 100000          // nodes
#define NE 3200000         // edges
#define NG 512             // graphs
#define NF 128             // input features
#define BN_EPS 1e-5f

// ---------------- scratch (device globals; no allocations allowed) ----------
__device__ float g_y1[NN * 32];    // x @ W_rel1, padded 30->32
__device__ float g_r1[NN * 32];    // x @ W_root1 + b1, padded
__device__ float g_agg1[NN * 32];  // segment-sum of y1 over edges
__device__ float g_y2[NN * 20];    // h @ W_rel2
__device__ float g_r2[NN * 20];    // h @ W_root2 + b2
__device__ float g_agg2[NN * 20];  // segment-sum of y2 over edges

// ---------------- helpers ----------------------------------------------------
__device__ __forceinline__ void red_add_v4(float* p, float4 v) {
    asm volatile("red.global.add.v4.f32 [%0], {%1, %2, %3, %4};"
                 :: "l"(__cvta_generic_to_global(p)),
                    "f"(v.x), "f"(v.y), "f"(v.z), "f"(v.w)
                 : "memory");
}

// ---------------- kernel 0: zero the aggregation buffers ---------------------
__global__ void k_zero(int n) {
    int gtid = blockIdx.x * blockDim.x + threadIdx.x;
    int n1 = n * 8;             // float4 count of agg1 (32 floats/node)
    int n2 = n * 5;             // float4 count of agg2 (20 floats/node)
    if (gtid < n1) {
        reinterpret_cast<float4*>(g_agg1)[gtid] = make_float4(0.f, 0.f, 0.f, 0.f);
    } else if (gtid < n1 + n2) {
        reinterpret_cast<float4*>(g_agg2)[gtid - n1] = make_float4(0.f, 0.f, 0.f, 0.f);
    }
}

// ---------------- kernel 1: node transform 1 (128 -> 30+30) ------------------
// y1 = x @ W_rel1 ; r1 = x @ W_root1 + b1
__global__ void __launch_bounds__(128) k_node1(
    const float* __restrict__ x,
    const float* __restrict__ Wrel,   // [128,30]
    const float* __restrict__ Wroot,  // [128,30]
    const float* __restrict__ b1,     // [30]
    int n)
{
    __shared__ float Ws[128 * 60];    // [k][j]: j<30 rel, j>=30 root
    for (int i = threadIdx.x; i < 128 * 30; i += 128) {
        int k = i / 30, j = i % 30;
        Ws[k * 60 + j]      = Wrel[i];
        Ws[k * 60 + 30 + j] = Wroot[i];
    }
    __syncthreads();

    int node = blockIdx.x * 128 + threadIdx.x;
    if (node >= n) return;

    float acc[60];
#pragma unroll
    for (int j = 0; j < 60; j++) acc[j] = 0.f;

    const float4* xr = reinterpret_cast<const float4*>(x) + node * 32;
#pragma unroll 2
    for (int k4 = 0; k4 < 32; k4++) {
        float4 xv = __ldg(xr + k4);
        const float* w = &Ws[k4 * 4 * 60];
#pragma unroll
        for (int j = 0; j < 60; j++) acc[j] += xv.x * w[j];
#pragma unroll
        for (int j = 0; j < 60; j++) acc[j] += xv.y * w[60 + j];
#pragma unroll
        for (int j = 0; j < 60; j++) acc[j] += xv.z * w[120 + j];
#pragma unroll
        for (int j = 0; j < 60; j++) acc[j] += xv.w * w[180 + j];
    }

    float* y = g_y1 + node * 32;
    float* r = g_r1 + node * 32;
#pragma unroll
    for (int j = 0; j < 30; j++) y[j] = acc[j];
    y[30] = 0.f; y[31] = 0.f;
#pragma unroll
    for (int j = 0; j < 30; j++) r[j] = acc[30 + j] + __ldg(&b1[j]);
}

// ---------------- kernel 2: edge scatter 1 (32 floats via 8x red.v4) ---------
__global__ void __launch_bounds__(256) k_scatter1(
    const int* __restrict__ ei, int nE)
{
    long long gtid = (long long)blockIdx.x * blockDim.x + threadIdx.x;
    if (gtid >= (long long)nE * 8) return;
    int e = (int)(gtid >> 3);
    int c = (int)(gtid & 7);
    int s = __ldg(&ei[e]);
    int d = __ldg(&ei[nE + e]);
    float4 v = __ldg(reinterpret_cast<const float4*>(g_y1) + s * 8 + c);
    red_add_v4(g_agg1 + d * 32 + c * 4, v);
}

// ---------------- kernel 3: node transform 2 ---------------------------------
// h = bn1(relu(agg1 + r1));  y2 = h @ W_rel2 ; r2 = h @ W_root2 + b2
__global__ void __launch_bounds__(128) k_node2(
    const float* __restrict__ bn1_g, const float* __restrict__ bn1_b,
    const float* __restrict__ bn1_m, const float* __restrict__ bn1_v,
    const float* __restrict__ Wrel2,   // [30,20]
    const float* __restrict__ Wroot2,  // [30,20]
    const float* __restrict__ b2,      // [20]
    int n)
{
    __shared__ float Ws[30 * 40];     // [k][j]: j<20 rel, j>=20 root
    __shared__ float sc1[30], sh1[30];
    for (int i = threadIdx.x; i < 30 * 20; i += 128) {
        int k = i / 20, j = i % 20;
        Ws[k * 40 + j]      = Wrel2[i];
        Ws[k * 40 + 20 + j] = Wroot2[i];
    }
    if (threadIdx.x < 30) {
        float sc = bn1_g[threadIdx.x] * rsqrtf(bn1_v[threadIdx.x] + BN_EPS);
        sc1[threadIdx.x] = sc;
        sh1[threadIdx.x] = bn1_b[threadIdx.x] - bn1_m[threadIdx.x] * sc;
    }
    __syncthreads();

    int node = blockIdx.x * 128 + threadIdx.x;
    if (node >= n) return;

    float h[30];
#pragma unroll
    for (int k = 0; k < 30; k++) {
        float a = __ldg(&g_agg1[node * 32 + k]) + __ldg(&g_r1[node * 32 + k]);
        h[k] = fmaxf(a, 0.f) * sc1[k] + sh1[k];
    }

#pragma unroll 4
    for (int j = 0; j < 40; j++) {
        float s = 0.f;
#pragma unroll
        for (int k = 0; k < 30; k++) s += h[k] * Ws[k * 40 + j];
        if (j < 20) g_y2[node * 20 + j] = s;
        else        g_r2[node * 20 + (j - 20)] = s + __ldg(&b2[j - 20]);
    }
}

// ---------------- kernel 4: edge scatter 2 (20 floats via 5x red.v4) ---------
__global__ void __launch_bounds__(256) k_scatter2(
    const int* __restrict__ ei, int nE)
{
    long long gtid = (long long)blockIdx.x * blockDim.x + threadIdx.x;
    if (gtid >= (long long)nE * 5) return;
    unsigned int u = (unsigned int)gtid;
    unsigned int e = u / 5u;
    unsigned int c = u - e * 5u;
    int s = __ldg(&ei[e]);
    int d = __ldg(&ei[nE + e]);
    float4 v = __ldg(reinterpret_cast<const float4*>(g_y2) + s * 5 + c);
    red_add_v4(g_agg2 + d * 20 + c * 4, v);
}

// ---------------- kernel 5: per-graph pooling + MLP head ---------------------
// h2 = bn2(relu(agg2 + r2)); pool max+mean over sorted batch ranges; head MLP.
__global__ void __launch_bounds__(32) k_pool_head(
    const int* __restrict__ batch, int n,
    const float* __restrict__ bn2_g, const float* __restrict__ bn2_b,
    const float* __restrict__ bn2_m, const float* __restrict__ bn2_v,
    const float* __restrict__ W1,    // [40,10]
    const float* __restrict__ bl1,   // [10]
    const float* __restrict__ W2,    // [10,1]
    const float* __restrict__ bl2,   // [1]
    float* __restrict__ out)
{
    int g = blockIdx.x;
    int lane = threadIdx.x;

    // binary search [start, end) of graph g in sorted batch
    int lo = 0, hi = n;
    while (lo < hi) { int mid = (lo + hi) >> 1; if (__ldg(&batch[mid]) < g) lo = mid + 1; else hi = mid; }
    int start = lo;
    lo = start; hi = n;
    while (lo < hi) { int mid = (lo + hi) >> 1; if (__ldg(&batch[mid]) < g + 1) lo = mid + 1; else hi = mid; }
    int end = lo;
    int cnt = end - start;

    float sc = 0.f, sh = 0.f;
    if (lane < 20) {
        sc = __ldg(&bn2_g[lane]) * rsqrtf(__ldg(&bn2_v[lane]) + BN_EPS);
        sh = __ldg(&bn2_b[lane]) - __ldg(&bn2_m[lane]) * sc;
    }

    float sum = 0.f, mx = -INFINITY;
    if (lane < 20) {
        for (int nd = start; nd < end; nd++) {
            float a = __ldg(&g_agg2[nd * 20 + lane]) + __ldg(&g_r2[nd * 20 + lane]);
            float v = fmaxf(a, 0.f) * sc + sh;
            sum += v;
            mx = fmaxf(mx, v);
        }
    }
    float mean = (lane < 20) ? (sum / fmaxf((float)cnt, 1.f)) : 0.f;
    if (cnt == 0 || lane >= 20) mx = 0.f;   // isfinite(gmax) -> 0 for empty graphs

    // head: z = [gmax(20), gmean(20)] @ W1 + b1 ; relu ; @ W2 + b2 ; sigmoid
    float o = 0.f;
#pragma unroll
    for (int j = 0; j < 10; j++) {
        float p = 0.f;
        if (lane < 20)
            p = mx * __ldg(&W1[lane * 10 + j]) + mean * __ldg(&W1[(lane + 20) * 10 + j]);
#pragma unroll
        for (int off = 16; off > 0; off >>= 1)
            p += __shfl_xor_sync(0xffffffffu, p, off);
        float z = fmaxf(p + __ldg(&bl1[j]), 0.f);
        o += z * __ldg(&W2[j]);
    }
    o += __ldg(&bl2[0]);
    float sig = 1.f / (1.f + expf(-o));
    if (lane == 0) out[g] = sig;
}

// ---------------- launch -----------------------------------------------------
extern "C" void kernel_launch(void* const* d_in, const int* in_sizes, int n_in,
                              void* d_out, int out_size) {
    const float* x      = (const float*)d_in[0];
    const int*   ei     = (const int*)  d_in[1];
    const int*   batch  = (const int*)  d_in[2];
    const float* Wrel1  = (const float*)d_in[3];
    const float* Wroot1 = (const float*)d_in[4];
    const float* b1     = (const float*)d_in[5];
    const float* bn1_g  = (const float*)d_in[6];
    const float* bn1_b  = (const float*)d_in[7];
    const float* bn1_m  = (const float*)d_in[8];
    const float* bn1_v  = (const float*)d_in[9];
    const float* Wrel2  = (const float*)d_in[10];
    const float* Wroot2 = (const float*)d_in[11];
    const float* b2     = (const float*)d_in[12];
    const float* bn2_g  = (const float*)d_in[13];
    const float* bn2_b  = (const float*)d_in[14];
    const float* bn2_m  = (const float*)d_in[15];
    const float* bn2_v  = (const float*)d_in[16];
    const float* W1     = (const float*)d_in[17];
    const float* bl1    = (const float*)d_in[18];
    const float* W2     = (const float*)d_in[19];
    const float* bl2    = (const float*)d_in[20];
    float* out = (float*)d_out;

    int n  = in_sizes[0] / NF;   // nodes
    int nE = in_sizes[1] / 2;    // edges

    // 0) zero agg buffers (13 float4 per node)
    {
        int total = n * 13;
        k_zero<<<(total + 255) / 256, 256>>>(n);
    }
    // 1) node transform 1
    k_node1<<<(n + 127) / 128, 128>>>(x, Wrel1, Wroot1, b1, n);
    // 2) edge scatter 1
    {
        long long total = (long long)nE * 8;
        k_scatter1<<<(unsigned)((total + 255) / 256), 256>>>(ei, nE);
    }
    // 3) node transform 2
    k_node2<<<(n + 127) / 128, 128>>>(bn1_g, bn1_b, bn1_m, bn1_v,
                                      Wrel2, Wroot2, b2, n);
    // 4) edge scatter 2
    {
        long long total = (long long)nE * 5;
        k_scatter2<<<(unsigned)((total + 255) / 256), 256>>>(ei, nE);
    }
    // 5) pooling + head (one warp per graph)
    k_pool_head<<<NG, 32>>>(batch, n, bn2_g, bn2_b, bn2_m, bn2_v,
                            W1, bl1, W2, bl2, out);
}